// round 5
// baseline (speedup 1.0000x reference)
#include <cuda_runtime.h>
#include <cuda_bf16.h>
#include <cstdint>

// out_means[b][d] = mean[d][labels[b][d]]; out_log_vars[b][d] = log_var[d][labels[b][d]]
// B = 2097152, N_DOMAINS = 8, MAX_CONCEPTS = 64.
// d_out: [means B*8 f32][log_vars B*8 f32].
//
// R5: software-pipelined multi-tile CTAs.
//  - each CTA processes NT=8 tiles of 256 samples
//  - labels for tile i+1 prefetched into registers before tile i's barrier
//    (read stream continuously outstanding)
//  - double-buffered smem staging; TMA bulk store of tile i overlaps gather
//    of tile i+1 (wait_group.read <= 1 before buffer reuse)

#define N_DOMAINS 8
#define MAX_CONCEPTS 64
#define TAB (N_DOMAINS * MAX_CONCEPTS)   // 512
#define BLK 256
#define TILE 256                         // samples per tile
#define NT 8                             // tiles per CTA

__global__ __launch_bounds__(BLK)
void concept_gauss_kernel(const int4* __restrict__ labels4,   // [B*2]
                          const float* __restrict__ mean,     // [512]
                          const float* __restrict__ log_var,  // [512]
                          float* __restrict__ out,            // [2*B*8]
                          int B, int tiles_per_cta)
{
    __shared__ float s_mean[TAB];
    __shared__ float s_var[TAB];
    // staging: [buffer][mean|var][TILE*8 floats] = 2*2*8KB = 32KB
    __shared__ alignas(128) float stg[2][2][TILE * N_DOMAINS];

    const int t = threadIdx.x;
    s_mean[t]       = mean[t];
    s_mean[t + 256] = mean[t + 256];
    s_var[t]        = log_var[t];
    s_var[t + 256]  = log_var[t + 256];
    // (table writes ordered before first gather by the barrier inside the loop)

    const long nTiles = ((long)B + TILE - 1) / TILE;
    const long tbeg = (long)blockIdx.x * tiles_per_cta;
    long tend = tbeg + tiles_per_cta;
    if (tend > nTiles) tend = nTiles;
    if (tbeg >= nTiles) { __syncthreads(); return; }

    // Prefetch labels for the first tile.
    int4 n0 = make_int4(0, 0, 0, 0), n1 = make_int4(0, 0, 0, 0);
    {
        long b = tbeg * TILE + t;
        if (b < B) {
            n0 = __ldcs(&labels4[2 * b]);
            n1 = __ldcs(&labels4[2 * b + 1]);
        }
    }

    int par = 0;
    for (long i = tbeg; i < tend; ++i) {
        const int4 a0 = n0, a1 = n1;

        // Prefetch next tile's labels (in flight across this tile's work).
        const long nb = (i + 1) * TILE + t;
        const bool pf = (i + 1 < tend) && (nb < B);
        if (pf) {
            n0 = __ldcs(&labels4[2 * nb]);
            n1 = __ldcs(&labels4[2 * nb + 1]);
        }

        const bool full = ((i + 1) * TILE) <= (long)B;

        if (full) {
            // Ensure buffer `par` is no longer being read by TMA:
            // <=1 pending group means everything except the newest (which
            // targets the other buffer) has completed its smem reads.
            if (t == 0)
                asm volatile("cp.async.bulk.wait_group.read 1;" ::: "memory");
            __syncthreads();

            float4* pm = reinterpret_cast<float4*>(&stg[par][0][t * N_DOMAINS]);
            float4* pv = reinterpret_cast<float4*>(&stg[par][1][t * N_DOMAINS]);

            pm[0] = make_float4(s_mean[0 * MAX_CONCEPTS + a0.x],
                                s_mean[1 * MAX_CONCEPTS + a0.y],
                                s_mean[2 * MAX_CONCEPTS + a0.z],
                                s_mean[3 * MAX_CONCEPTS + a0.w]);
            pm[1] = make_float4(s_mean[4 * MAX_CONCEPTS + a1.x],
                                s_mean[5 * MAX_CONCEPTS + a1.y],
                                s_mean[6 * MAX_CONCEPTS + a1.z],
                                s_mean[7 * MAX_CONCEPTS + a1.w]);
            pv[0] = make_float4(s_var[0 * MAX_CONCEPTS + a0.x],
                                s_var[1 * MAX_CONCEPTS + a0.y],
                                s_var[2 * MAX_CONCEPTS + a0.z],
                                s_var[3 * MAX_CONCEPTS + a0.w]);
            pv[1] = make_float4(s_var[4 * MAX_CONCEPTS + a1.x],
                                s_var[5 * MAX_CONCEPTS + a1.y],
                                s_var[6 * MAX_CONCEPTS + a1.z],
                                s_var[7 * MAX_CONCEPTS + a1.w]);

            __syncthreads();

            if (t == 0) {
                asm volatile("fence.proxy.async.shared::cta;" ::: "memory");

                uint32_t sm_m, sm_v;
                asm("{ .reg .u64 a; cvta.to.shared.u64 a, %1; cvt.u32.u64 %0, a; }"
                    : "=r"(sm_m) : "l"(&stg[par][0][0]));
                asm("{ .reg .u64 a; cvta.to.shared.u64 a, %1; cvt.u32.u64 %0, a; }"
                    : "=r"(sm_v) : "l"(&stg[par][1][0]));

                const uint32_t bytes = TILE * N_DOMAINS * sizeof(float);  // 8192
                float* dst_m = out + i * (long)(TILE * N_DOMAINS);
                float* dst_v = out + (long)B * N_DOMAINS + i * (long)(TILE * N_DOMAINS);

                asm volatile(
                    "cp.async.bulk.global.shared::cta.bulk_group [%0], [%1], %2;"
                    :: "l"(dst_m), "r"(sm_m), "r"(bytes) : "memory");
                asm volatile(
                    "cp.async.bulk.global.shared::cta.bulk_group [%0], [%1], %2;"
                    :: "l"(dst_v), "r"(sm_v), "r"(bytes) : "memory");
                asm volatile("cp.async.bulk.commit_group;" ::: "memory");
            }
            par ^= 1;
        } else {
            // Partial tail tile: direct stores (unused for B = 2^21).
            long b = i * TILE + t;
            if (b < B) {
                int4 l0 = __ldcs(&labels4[2 * b]);
                int4 l1 = __ldcs(&labels4[2 * b + 1]);
                float4* o = reinterpret_cast<float4*>(out);
                long vb = 2L * B;  // float4 units
                o[2 * b]     = make_float4(s_mean[0 * MAX_CONCEPTS + l0.x],
                                           s_mean[1 * MAX_CONCEPTS + l0.y],
                                           s_mean[2 * MAX_CONCEPTS + l0.z],
                                           s_mean[3 * MAX_CONCEPTS + l0.w]);
                o[2 * b + 1] = make_float4(s_mean[4 * MAX_CONCEPTS + l1.x],
                                           s_mean[5 * MAX_CONCEPTS + l1.y],
                                           s_mean[6 * MAX_CONCEPTS + l1.z],
                                           s_mean[7 * MAX_CONCEPTS + l1.w]);
                o[vb + 2 * b]     = make_float4(s_var[0 * MAX_CONCEPTS + l0.x],
                                                s_var[1 * MAX_CONCEPTS + l0.y],
                                                s_var[2 * MAX_CONCEPTS + l0.z],
                                                s_var[3 * MAX_CONCEPTS + l0.w]);
                o[vb + 2 * b + 1] = make_float4(s_var[4 * MAX_CONCEPTS + l1.x],
                                                s_var[5 * MAX_CONCEPTS + l1.y],
                                                s_var[6 * MAX_CONCEPTS + l1.z],
                                                s_var[7 * MAX_CONCEPTS + l1.w]);
            }
        }
    }

    // Drain: smem must stay allocated until TMA finishes reading it.
    if (t == 0)
        asm volatile("cp.async.bulk.wait_group.read 0;" ::: "memory");
    __syncthreads();
}

extern "C" void kernel_launch(void* const* d_in, const int* in_sizes, int n_in,
                              void* d_out, int out_size) {
    const int4*  labels4 = (const int4*)d_in[0];
    const float* mean    = (const float*)d_in[1];
    const float* log_var = (const float*)d_in[2];
    float* out = (float*)d_out;

    int B = in_sizes[0] / N_DOMAINS;             // 2097152
    long nTiles = ((long)B + TILE - 1) / TILE;   // 8192
    int blocks = (int)((nTiles + NT - 1) / NT);  // 1024
    concept_gauss_kernel<<<blocks, BLK>>>(labels4, mean, log_var, out, B, NT);
}

// round 6
// speedup vs baseline: 1.1179x; 1.1179x over previous
#include <cuda_runtime.h>
#include <cuda_bf16.h>
#include <cstdint>

// out_means[b][d] = mean[d][labels[b][d]]; out_log_vars[b][d] = log_var[d][labels[b][d]]
// B = 2097152, N_DOMAINS = 8, MAX_CONCEPTS = 64.
// d_out: [means B*8 f32][log_vars B*8 f32].
//
// R6: R3's winning shape (256 samples/CTA, 8192 CTAs) with the CTA-tail cut:
//  - per-WARP TMA bulk stores (1KB mean + 1KB var per warp) issued right
//    after __syncwarp — no second CTA barrier, no slowest-warp convergence
//  - wait_group.read (smem-read completion only), waited by lane 0 of each
//    warp; remaining lanes exit immediately (smem lives while lane 0 does)

#define N_DOMAINS 8
#define MAX_CONCEPTS 64
#define TAB (N_DOMAINS * MAX_CONCEPTS)   // 512
#define BLK 256
#define WARPS (BLK / 32)

__global__ __launch_bounds__(BLK)
void concept_gauss_kernel(const int4* __restrict__ labels4,   // [B*2]
                          const float* __restrict__ mean,     // [512]
                          const float* __restrict__ log_var,  // [512]
                          float* __restrict__ out,            // [2*B*8]
                          int B)
{
    __shared__ float s_mean[TAB];
    __shared__ float s_var[TAB];
    __shared__ alignas(128) float st_mean[BLK * N_DOMAINS];  // 8 KB, 1KB/warp
    __shared__ alignas(128) float st_var[BLK * N_DOMAINS];   // 8 KB, 1KB/warp

    const int t = threadIdx.x;
    const int w = t >> 5;
    const int lane = t & 31;

    // Cooperative table load (2 KB each), then the only CTA-wide barrier.
    s_mean[t]       = __ldg(&mean[t]);
    s_mean[t + 256] = __ldg(&mean[t + 256]);
    s_var[t]        = __ldg(&log_var[t]);
    s_var[t + 256]  = __ldg(&log_var[t + 256]);
    __syncthreads();

    const long base = (long)blockIdx.x * BLK;
    const long b    = base + t;
    const bool full_block = (base + BLK) <= (long)B;

    if (full_block) {
        int4 l0 = __ldcs(&labels4[2 * b]);
        int4 l1 = __ldcs(&labels4[2 * b + 1]);

        float4* pm = reinterpret_cast<float4*>(&st_mean[t * N_DOMAINS]);
        float4* pv = reinterpret_cast<float4*>(&st_var[t * N_DOMAINS]);

        pm[0] = make_float4(s_mean[0 * MAX_CONCEPTS + l0.x],
                            s_mean[1 * MAX_CONCEPTS + l0.y],
                            s_mean[2 * MAX_CONCEPTS + l0.z],
                            s_mean[3 * MAX_CONCEPTS + l0.w]);
        pm[1] = make_float4(s_mean[4 * MAX_CONCEPTS + l1.x],
                            s_mean[5 * MAX_CONCEPTS + l1.y],
                            s_mean[6 * MAX_CONCEPTS + l1.z],
                            s_mean[7 * MAX_CONCEPTS + l1.w]);
        pv[0] = make_float4(s_var[0 * MAX_CONCEPTS + l0.x],
                            s_var[1 * MAX_CONCEPTS + l0.y],
                            s_var[2 * MAX_CONCEPTS + l0.z],
                            s_var[3 * MAX_CONCEPTS + l0.w]);
        pv[1] = make_float4(s_var[4 * MAX_CONCEPTS + l1.x],
                            s_var[5 * MAX_CONCEPTS + l1.y],
                            s_var[6 * MAX_CONCEPTS + l1.z],
                            s_var[7 * MAX_CONCEPTS + l1.w]);

        // Warp-local completion of the 1KB staging slices this warp owns.
        __syncwarp();

        if (lane == 0) {
            // Order this warp's generic-proxy STS before async-proxy TMA reads.
            asm volatile("fence.proxy.async.shared::cta;" ::: "memory");

            uint32_t sm_m, sm_v;
            asm("{ .reg .u64 a; cvta.to.shared.u64 a, %1; cvt.u32.u64 %0, a; }"
                : "=r"(sm_m) : "l"(&st_mean[w * 32 * N_DOMAINS]));
            asm("{ .reg .u64 a; cvta.to.shared.u64 a, %1; cvt.u32.u64 %0, a; }"
                : "=r"(sm_v) : "l"(&st_var[w * 32 * N_DOMAINS]));

            const uint32_t bytes = 32 * N_DOMAINS * sizeof(float);  // 1024
            float* dst_m = out + (base + w * 32) * N_DOMAINS;
            float* dst_v = out + (long)B * N_DOMAINS + (base + w * 32) * N_DOMAINS;

            asm volatile(
                "cp.async.bulk.global.shared::cta.bulk_group [%0], [%1], %2;"
                :: "l"(dst_m), "r"(sm_m), "r"(bytes) : "memory");
            asm volatile(
                "cp.async.bulk.global.shared::cta.bulk_group [%0], [%1], %2;"
                :: "l"(dst_v), "r"(sm_v), "r"(bytes) : "memory");
            asm volatile("cp.async.bulk.commit_group;" ::: "memory");
            // Wait only for TMA to finish READING the staging smem, then exit.
            // Lane 0's residency keeps the CTA (and its smem) alive meanwhile;
            // all other lanes exit immediately.
            asm volatile("cp.async.bulk.wait_group.read 0;" ::: "memory");
        }
    } else {
        // Tail (unused for B = 2^21): direct stores.
        if (b < B) {
            int4 l0 = __ldcs(&labels4[2 * b]);
            int4 l1 = __ldcs(&labels4[2 * b + 1]);
            float4* o = reinterpret_cast<float4*>(out);
            long vb = 2L * B;  // float4 units
            o[2 * b]     = make_float4(s_mean[0 * MAX_CONCEPTS + l0.x],
                                       s_mean[1 * MAX_CONCEPTS + l0.y],
                                       s_mean[2 * MAX_CONCEPTS + l0.z],
                                       s_mean[3 * MAX_CONCEPTS + l0.w]);
            o[2 * b + 1] = make_float4(s_mean[4 * MAX_CONCEPTS + l1.x],
                                       s_mean[5 * MAX_CONCEPTS + l1.y],
                                       s_mean[6 * MAX_CONCEPTS + l1.z],
                                       s_mean[7 * MAX_CONCEPTS + l1.w]);
            o[vb + 2 * b]     = make_float4(s_var[0 * MAX_CONCEPTS + l0.x],
                                            s_var[1 * MAX_CONCEPTS + l0.y],
                                            s_var[2 * MAX_CONCEPTS + l0.z],
                                            s_var[3 * MAX_CONCEPTS + l0.w]);
            o[vb + 2 * b + 1] = make_float4(s_var[4 * MAX_CONCEPTS + l1.x],
                                            s_var[5 * MAX_CONCEPTS + l1.y],
                                            s_var[6 * MAX_CONCEPTS + l1.z],
                                            s_var[7 * MAX_CONCEPTS + l1.w]);
        }
    }
}

extern "C" void kernel_launch(void* const* d_in, const int* in_sizes, int n_in,
                              void* d_out, int out_size) {
    const int4*  labels4 = (const int4*)d_in[0];
    const float* mean    = (const float*)d_in[1];
    const float* log_var = (const float*)d_in[2];
    float* out = (float*)d_out;

    int B = in_sizes[0] / N_DOMAINS;   // 2097152
    int blocks = (B + BLK - 1) / BLK;  // 8192
    concept_gauss_kernel<<<blocks, BLK>>>(labels4, mean, log_var, out, B);
}